// round 7
// baseline (speedup 1.0000x reference)
#include <cuda_runtime.h>
#include <math.h>

#define BB   16
#define NNODE 1000
#define EEDGE 4000
#define DDIM 256
#define HHEAD 4
#define HDDIM 1024
#define LSEQ 64
#define AACT 128
#define OHID 256
#define G3   768

// ---------------- scratch (device globals; no allocation allowed) ----------------
__device__ float d_x[BB*NNODE*DDIM];
__device__ float d_eafeat[BB*EEDGE*DDIM];
__device__ float d_q[BB*NNODE*HDDIM];
__device__ float d_kn[BB*NNODE*HDDIM];
__device__ float d_vn[BB*NNODE*HDDIM];
__device__ float d_skip[BB*NNODE*HDDIM];
__device__ float d_ep[BB*EEDGE*HDDIM];
__device__ float d_alpha[BB*EEDGE*HHEAD];
__device__ float d_hbuf[BB*NNODE*HDDIM];
__device__ float d_gr[BB*NNODE*DDIM];
__device__ float d_invemb[BB*LSEQ*DDIM];
__device__ float d_invh[BB*LSEQ*DDIM];
__device__ float d_gx[BB*LSEQ*G3];
__device__ float d_invstate[BB*OHID];
__device__ float d_aaemb[BB*AACT*DDIM];
// CSR
__device__ int d_cnt[BB*NNODE];
__device__ int d_off[BB*NNODE];
__device__ int d_cur[BB*NNODE];
__device__ int d_elist[BB*EEDGE];

// ---------------- f32x2 helpers ----------------
__device__ __forceinline__ unsigned long long pk2(float x, float y) {
    unsigned long long r;
    asm("mov.b64 %0, {%1, %2};" : "=l"(r) : "f"(x), "f"(y));
    return r;
}
#define FMA2(c, a, b) asm("fma.rn.f32x2 %0, %1, %2, %0;" : "+l"(c) : "l"(a), "l"(b))
#define UNPK2(lo, hi, v) asm("mov.b64 {%0, %1}, %2;" : "=f"(lo), "=f"(hi) : "l"(v))

// ---------------- gathers ----------------
__global__ void gather_rows(float* __restrict__ out, const float* __restrict__ emb,
                            const int* __restrict__ idx) {
    int r = blockIdx.x;
    int t = idx[r];
    const float4* src = (const float4*)(emb + (size_t)t * DDIM);
    float4* dst = (float4*)(out + (size_t)r * DDIM);
    dst[threadIdx.x] = src[threadIdx.x];
}

__global__ void mixed_embed(float* __restrict__ out, const float* __restrict__ emb,
                            const int* __restrict__ tok, const int* __restrict__ node,
                            int perB) {
    int r = blockIdx.x;
    int b = r / perB;
    int t = tok[r];
    int nd = node[r];
    const float* e1 = emb + (size_t)t * DDIM;
    const float* e2 = d_gr + (size_t)(b * NNODE + nd) * DDIM;
    int c = threadIdx.x;
    out[(size_t)r * DDIM + c] = e1[c] + e2[c];
}

// ---------------- gemm128: C[M,N]=A[M,K]@W[K,N] (+bias)(+relu), 128x128x16, 8x8/thread, f32x2 ----------------
__global__ __launch_bounds__(256, 2)
void gemm128(const float* __restrict__ A, const float* __restrict__ W,
             const float* __restrict__ bias, float* __restrict__ C,
             int M, int Nn, int K, int relu) {
    __shared__ float As[2][16][132];
    __shared__ float Bs[2][16][132];
    int tid = threadIdx.x;
    int bm = blockIdx.y * 128, bn = blockIdx.x * 128;
    int tx = tid & 15, ty = tid >> 4;
    int arow = tid >> 1, ac = (tid & 1) * 8;
    int bk = tid >> 4, bc = (tid & 15) * 8;
    const float* Ag = A + (size_t)(bm + arow) * K + ac;
    const float* Wg = W + (size_t)bk * Nn + bn + bc;

    unsigned long long acc[8][4];
#pragma unroll
    for (int i = 0; i < 8; i++)
#pragma unroll
        for (int j = 0; j < 4; j++) acc[i][j] = 0ULL;

    // first tile -> buf 0
    float4 ra0 = *(const float4*)(Ag);
    float4 ra1 = *(const float4*)(Ag + 4);
    float4 rb0 = *(const float4*)(Wg);
    float4 rb1 = *(const float4*)(Wg + 4);
    As[0][ac + 0][arow] = ra0.x; As[0][ac + 1][arow] = ra0.y;
    As[0][ac + 2][arow] = ra0.z; As[0][ac + 3][arow] = ra0.w;
    As[0][ac + 4][arow] = ra1.x; As[0][ac + 5][arow] = ra1.y;
    As[0][ac + 6][arow] = ra1.z; As[0][ac + 7][arow] = ra1.w;
    *(float4*)&Bs[0][bk][bc] = rb0;
    *(float4*)&Bs[0][bk][bc + 4] = rb1;
    __syncthreads();

    int ntile = K >> 4;
    for (int t = 0; t < ntile; t++) {
        int buf = t & 1;
        if (t + 1 < ntile) {
            const float* Ap = Ag + (t + 1) * 16;
            const float* Wp_ = Wg + (size_t)(t + 1) * 16 * Nn;
            ra0 = *(const float4*)(Ap);
            ra1 = *(const float4*)(Ap + 4);
            rb0 = *(const float4*)(Wp_);
            rb1 = *(const float4*)(Wp_ + 4);
        }
#pragma unroll
        for (int kk = 0; kk < 16; kk++) {
            float4 A0 = *(const float4*)&As[buf][kk][ty * 4];
            float4 A1 = *(const float4*)&As[buf][kk][64 + ty * 4];
            float4 B0 = *(const float4*)&Bs[buf][kk][tx * 4];
            float4 B1 = *(const float4*)&Bs[buf][kk][64 + tx * 4];
            unsigned long long b0 = pk2(B0.x, B0.y), b1 = pk2(B0.z, B0.w);
            unsigned long long b2 = pk2(B1.x, B1.y), b3 = pk2(B1.z, B1.w);
            float av[8] = {A0.x, A0.y, A0.z, A0.w, A1.x, A1.y, A1.z, A1.w};
#pragma unroll
            for (int i = 0; i < 8; i++) {
                unsigned long long a2 = pk2(av[i], av[i]);
                FMA2(acc[i][0], a2, b0);
                FMA2(acc[i][1], a2, b1);
                FMA2(acc[i][2], a2, b2);
                FMA2(acc[i][3], a2, b3);
            }
        }
        if (t + 1 < ntile) {
            int nb = buf ^ 1;
            As[nb][ac + 0][arow] = ra0.x; As[nb][ac + 1][arow] = ra0.y;
            As[nb][ac + 2][arow] = ra0.z; As[nb][ac + 3][arow] = ra0.w;
            As[nb][ac + 4][arow] = ra1.x; As[nb][ac + 5][arow] = ra1.y;
            As[nb][ac + 6][arow] = ra1.z; As[nb][ac + 7][arow] = ra1.w;
            *(float4*)&Bs[nb][bk][bc] = rb0;
            *(float4*)&Bs[nb][bk][bc + 4] = rb1;
        }
        __syncthreads();
    }

#pragma unroll
    for (int i = 0; i < 8; i++) {
        int row = bm + ((i < 4) ? (ty * 4 + i) : (64 + ty * 4 + i - 4));
#pragma unroll
        for (int half = 0; half < 2; half++) {
            int col = bn + half * 64 + tx * 4;
            float o0, o1, o2, o3;
            UNPK2(o0, o1, acc[i][half * 2]);
            UNPK2(o2, o3, acc[i][half * 2 + 1]);
            if (bias) {
                o0 += bias[col]; o1 += bias[col + 1];
                o2 += bias[col + 2]; o3 += bias[col + 3];
            }
            if (relu) {
                o0 = fmaxf(o0, 0.f); o1 = fmaxf(o1, 0.f);
                o2 = fmaxf(o2, 0.f); o3 = fmaxf(o3, 0.f);
            }
            *(float4*)&C[(size_t)row * Nn + col] = make_float4(o0, o1, o2, o3);
        }
    }
}

// ---------------- gemm64 (kept for the small W^T GEMM: gx = invh @ W_ih^T) ----------------
template<bool WT>
__global__ void gemm64(const float* __restrict__ A, const float* __restrict__ W,
                       const float* __restrict__ bias, float* __restrict__ C,
                       int M, int Nn, int K, int relu) {
    __shared__ float As[16][68];
    __shared__ float Ws[16][68];
    int tid = threadIdx.x;
    int bm = blockIdx.y * 64, bn = blockIdx.x * 64;
    int tm = (tid >> 4) * 4, tn = (tid & 15) * 4;
    float acc[4][4];
#pragma unroll
    for (int i = 0; i < 4; i++)
#pragma unroll
        for (int j = 0; j < 4; j++) acc[i][j] = 0.f;

    int la_m = tid >> 2, la_k = (tid & 3) * 4;
    for (int k0 = 0; k0 < K; k0 += 16) {
        float4 a4 = *(const float4*)&A[(size_t)(bm + la_m) * K + k0 + la_k];
        As[la_k + 0][la_m] = a4.x; As[la_k + 1][la_m] = a4.y;
        As[la_k + 2][la_m] = a4.z; As[la_k + 3][la_m] = a4.w;
        if (!WT) {
            int wk = tid >> 4, wn = (tid & 15) * 4;
            float4 w4 = *(const float4*)&W[(size_t)(k0 + wk) * Nn + bn + wn];
            *(float4*)&Ws[wk][wn] = w4;
        } else {
            int wn = tid >> 2, wk = (tid & 3) * 4;
            float4 w4 = *(const float4*)&W[(size_t)(bn + wn) * K + k0 + wk];
            Ws[wk + 0][wn] = w4.x; Ws[wk + 1][wn] = w4.y;
            Ws[wk + 2][wn] = w4.z; Ws[wk + 3][wn] = w4.w;
        }
        __syncthreads();
#pragma unroll
        for (int kk = 0; kk < 16; kk++) {
            float4 a = *(const float4*)&As[kk][tm];
            float4 w = *(const float4*)&Ws[kk][tn];
            acc[0][0] += a.x * w.x; acc[0][1] += a.x * w.y; acc[0][2] += a.x * w.z; acc[0][3] += a.x * w.w;
            acc[1][0] += a.y * w.x; acc[1][1] += a.y * w.y; acc[1][2] += a.y * w.z; acc[1][3] += a.y * w.w;
            acc[2][0] += a.z * w.x; acc[2][1] += a.z * w.y; acc[2][2] += a.z * w.z; acc[2][3] += a.z * w.w;
            acc[3][0] += a.w * w.x; acc[3][1] += a.w * w.y; acc[3][2] += a.w * w.z; acc[3][3] += a.w * w.w;
        }
        __syncthreads();
    }
#pragma unroll
    for (int i = 0; i < 4; i++) {
#pragma unroll
        for (int j = 0; j < 4; j++) {
            float v = acc[i][j];
            if (bias) v += bias[bn + tn + j];
            if (relu) v = fmaxf(v, 0.f);
            C[(size_t)(bm + tm + i) * Nn + bn + tn + j] = v;
        }
    }
}

// ---------------- CSR build ----------------
__global__ void zero_cnt() {
    int i = blockIdx.x * blockDim.x + threadIdx.x;
    if (i < BB * NNODE) d_cnt[i] = 0;
}

__global__ void count_k(const int* __restrict__ eidx) {
    int be = blockIdx.x * blockDim.x + threadIdx.x;
    if (be >= BB * EEDGE) return;
    int b = be / EEDGE, e = be - b * EEDGE;
    int dst = eidx[(size_t)(b * 2 + 1) * EEDGE + e];
    atomicAdd(&d_cnt[b * NNODE + dst], 1);
}

__global__ void scan_k() {
    __shared__ int sbuf[1024];
    __shared__ int carry;
    int t = threadIdx.x;
    if (t == 0) carry = 0;
    __syncthreads();
    for (int c = 0; c < 16; c++) {
        int i = c * 1024 + t;
        int v = (i < BB * NNODE) ? d_cnt[i] : 0;
        sbuf[t] = v;
        __syncthreads();
        for (int off = 1; off < 1024; off <<= 1) {
            int x = 0;
            if (t >= off) x = sbuf[t - off];
            __syncthreads();
            if (t >= off) sbuf[t] += x;
            __syncthreads();
        }
        if (i < BB * NNODE) {
            int excl = carry + sbuf[t] - v;
            d_off[i] = excl;
            d_cur[i] = excl;
        }
        __syncthreads();
        if (t == 1023) carry += sbuf[1023];
        __syncthreads();
    }
}

__global__ void fill_k(const int* __restrict__ eidx) {
    int be = blockIdx.x * blockDim.x + threadIdx.x;
    if (be >= BB * EEDGE) return;
    int b = be / EEDGE, e = be - b * EEDGE;
    int dst = eidx[(size_t)(b * 2 + 1) * EEDGE + e];
    int pos = atomicAdd(&d_cur[b * NNODE + dst], 1);
    d_elist[pos] = be;
}

// ---------------- fused per-node attention (alpha + softmax + aggregate + skip + relu) ----------------
__global__ void node_attn(const int* __restrict__ eidx) {
    int nid = blockIdx.x;             // b*NNODE + node
    int b = nid / NNODE;
    int t = threadIdx.x;              // 256; thread handles cols j*256+t, head j
    float* hb = d_hbuf + (size_t)nid * HDDIM;
    const float* sk = d_skip + (size_t)nid * HDDIM;
    int deg = d_cnt[nid];
    if (deg == 0) {
#pragma unroll
        for (int j = 0; j < 4; j++)
            hb[j * 256 + t] = fmaxf(sk[j * 256 + t], 0.f);
        return;
    }
    int beg = d_off[nid];
    int lane = t & 31, warp = t >> 5;

    float qv[4];
    const float* qp = d_q + (size_t)nid * HDDIM;
#pragma unroll
    for (int j = 0; j < 4; j++) qv[j] = qp[j * 256 + t];

    __shared__ float wsum[8][4];
    __shared__ float mh[4], sh[4];
    if (t < 4) { mh[t] = -3.402823466e38f; sh[t] = 0.f; }
    __syncthreads();

    // pass 1: alpha + online softmax stats
    for (int ei = beg; ei < beg + deg; ei++) {
        int be = d_elist[ei];
        int e = be - b * EEDGE;
        int src = eidx[(size_t)(b * 2) * EEDGE + e];
        const float* kp = d_kn + (size_t)(b * NNODE + src) * HDDIM;
        const float* ep = d_ep + (size_t)be * HDDIM;
        float p[4];
#pragma unroll
        for (int j = 0; j < 4; j++)
            p[j] = qv[j] * (kp[j * 256 + t] + ep[j * 256 + t]);
#pragma unroll
        for (int o = 16; o > 0; o >>= 1) {
#pragma unroll
            for (int j = 0; j < 4; j++)
                p[j] += __shfl_xor_sync(0xffffffffu, p[j], o);
        }
        if (lane == 0) {
#pragma unroll
            for (int j = 0; j < 4; j++) wsum[warp][j] = p[j];
        }
        __syncthreads();
        if (t < 4) {
            float a = 0.f;
#pragma unroll
            for (int w = 0; w < 8; w++) a += wsum[w][t];
            a *= 0.0625f;   // 1/sqrt(256)
            d_alpha[(size_t)ei * 4 + t] = a;
            float m = mh[t];
            float mn = fmaxf(m, a);
            sh[t] = sh[t] * expf(m - mn) + expf(a - mn);
            mh[t] = mn;
        }
        __syncthreads();
    }

    float m[4], sinv[4];
#pragma unroll
    for (int j = 0; j < 4; j++) { m[j] = mh[j]; sinv[j] = 1.f / sh[j]; }

    // pass 2: weighted aggregation
    float acc[4] = {0.f, 0.f, 0.f, 0.f};
    for (int ei = beg; ei < beg + deg; ei++) {
        int be = d_elist[ei];
        int e = be - b * EEDGE;
        int src = eidx[(size_t)(b * 2) * EEDGE + e];
        const float* vp = d_vn + (size_t)(b * NNODE + src) * HDDIM;
        const float* ep = d_ep + (size_t)be * HDDIM;
#pragma unroll
        for (int j = 0; j < 4; j++) {
            float w = expf(d_alpha[(size_t)ei * 4 + j] - m[j]) * sinv[j];
            acc[j] += w * (vp[j * 256 + t] + ep[j * 256 + t]);
        }
    }
#pragma unroll
    for (int j = 0; j < 4; j++)
        hb[j * 256 + t] = fmaxf(acc[j] + sk[j * 256 + t], 0.f);
}

// ---------------- GRU (one block per batch element, f32x2 matvec) ----------------
__global__ void gru_kernel(const float* __restrict__ Whh, const float* __restrict__ bhh) {
    int b = blockIdx.x;
    __shared__ __align__(16) float hsh[OHID];
    __shared__ float gsh[G3];
    int t = threadIdx.x;        // 768
    if (t < OHID) hsh[t] = 0.f;
    __syncthreads();
    const float2* wr2 = (const float2*)(Whh + (size_t)t * OHID);
    const float2* h2p = (const float2*)hsh;
    float bg = bhh[t];
    for (int l = 0; l < LSEQ; l++) {
        unsigned long long acc2 = 0ULL;
#pragma unroll 16
        for (int k = 0; k < OHID / 2; k++) {
            float2 w = wr2[k], h = h2p[k];
            unsigned long long wp = pk2(w.x, w.y), hp = pk2(h.x, h.y);
            FMA2(acc2, wp, hp);
        }
        float lo, hi;
        UNPK2(lo, hi, acc2);
        gsh[t] = bg + lo + hi;
        __syncthreads();
        if (t < OHID) {
            const float* gx = d_gx + (size_t)(b * LSEQ + l) * G3;
            float r = 1.f / (1.f + expf(-(gx[t] + gsh[t])));
            float z = 1.f / (1.f + expf(-(gx[OHID + t] + gsh[OHID + t])));
            float c = tanhf(gx[2 * OHID + t] + r * gsh[2 * OHID + t]);
            hsh[t] = (1.f - z) * c + z * hsh[t];
        }
        __syncthreads();
    }
    if (t < OHID) d_invstate[b * OHID + t] = hsh[t];
}

// ---------------- final scoring ----------------
__global__ void aa_score(const float* __restrict__ Wap, const float* __restrict__ bap,
                         const float* __restrict__ Wab, const float* __restrict__ bab,
                         const float* __restrict__ mask, float* __restrict__ out) {
    int ba = blockIdx.x;                 // B*A
    int b = ba / AACT;
    __shared__ float ash[DDIM];
    __shared__ float red[DDIM];
    int o = threadIdx.x;                 // 256
    ash[o] = d_aaemb[(size_t)ba * DDIM + o];
    __syncthreads();
    float acc = 0.f;
#pragma unroll 4
    for (int dd = 0; dd < DDIM; dd++) acc += ash[dd] * Wap[(size_t)dd * OHID + o];
    float p = acc + bap[o];
    float val = p * d_invstate[b * OHID + o];
    val += ash[o] * Wab[o];
    red[o] = val;
    __syncthreads();
    for (int s = 128; s > 0; s >>= 1) {
        if (o < s) red[o] += red[o + s];
        __syncthreads();
    }
    if (o == 0) {
        float mk = fmaxf(logf(mask[ba]), -3.402823466e38f);
        out[ba] = red[0] + bab[0] + mk;
    }
}

// ---------------- launch ----------------
extern "C" void kernel_launch(void* const* d_in, const int* in_sizes, int n_in,
                              void* d_out, int out_size) {
    const int* node_tokens = (const int*)d_in[0];
    const int* edge_tokens = (const int*)d_in[1];
    const int* edge_index  = (const int*)d_in[2];
    const int* inv_token   = (const int*)d_in[3];
    const int* inv_node    = (const int*)d_in[4];
    const int* aa_token    = (const int*)d_in[5];
    const int* aa_node     = (const int*)d_in[6];
    const float* action_mask = (const float*)d_in[7];
    const float* emb  = (const float*)d_in[8];
    const float* Wq   = (const float*)d_in[9];
    const float* bq   = (const float*)d_in[10];
    const float* Wk   = (const float*)d_in[11];
    const float* bk   = (const float*)d_in[12];
    const float* Wv   = (const float*)d_in[13];
    const float* bv   = (const float*)d_in[14];
    const float* We   = (const float*)d_in[15];
    const float* Wskip = (const float*)d_in[16];
    const float* bskip = (const float*)d_in[17];
    const float* W1   = (const float*)d_in[18];
    const float* b1   = (const float*)d_in[19];
    const float* Wp   = (const float*)d_in[20];
    const float* bp   = (const float*)d_in[21];
    const float* W_ih = (const float*)d_in[22];
    const float* W_hh = (const float*)d_in[23];
    const float* b_ih = (const float*)d_in[24];
    const float* b_hh = (const float*)d_in[25];
    const float* Wab  = (const float*)d_in[26];
    const float* bab  = (const float*)d_in[27];
    const float* Wap  = (const float*)d_in[28];
    const float* bap  = (const float*)d_in[29];
    float* out = (float*)d_out;

    float* p_x      = nullptr; cudaGetSymbolAddress((void**)&p_x, d_x);
    float* p_ea     = nullptr; cudaGetSymbolAddress((void**)&p_ea, d_eafeat);
    float* p_q      = nullptr; cudaGetSymbolAddress((void**)&p_q, d_q);
    float* p_kn     = nullptr; cudaGetSymbolAddress((void**)&p_kn, d_kn);
    float* p_vn     = nullptr; cudaGetSymbolAddress((void**)&p_vn, d_vn);
    float* p_skip   = nullptr; cudaGetSymbolAddress((void**)&p_skip, d_skip);
    float* p_ep     = nullptr; cudaGetSymbolAddress((void**)&p_ep, d_ep);
    float* p_h      = nullptr; cudaGetSymbolAddress((void**)&p_h, d_hbuf);
    float* p_gr     = nullptr; cudaGetSymbolAddress((void**)&p_gr, d_gr);
    float* p_invemb = nullptr; cudaGetSymbolAddress((void**)&p_invemb, d_invemb);
    float* p_invh   = nullptr; cudaGetSymbolAddress((void**)&p_invh, d_invh);
    float* p_gx     = nullptr; cudaGetSymbolAddress((void**)&p_gx, d_gx);
    float* p_aaemb  = nullptr; cudaGetSymbolAddress((void**)&p_aaemb, d_aaemb);

    // 1. gathers
    gather_rows<<<BB * NNODE, 64>>>(p_x, emb, node_tokens);
    gather_rows<<<BB * EEDGE, 64>>>(p_ea, emb, edge_tokens);

    // CSR build (only needs edge_index)
    zero_cnt<<<(BB * NNODE + 255) / 256, 256>>>();
    count_k<<<(BB * EEDGE + 255) / 256, 256>>>(edge_index);
    scan_k<<<1, 1024>>>();
    fill_k<<<(BB * EEDGE + 255) / 256, 256>>>(edge_index);

    // 2. node / edge projections (128x128 f32x2 GEMM)
    {
        dim3 g(HDDIM / 128, (BB * NNODE) / 128);
        gemm128<<<g, 256>>>(p_x, Wq, bq, p_q, BB * NNODE, HDDIM, DDIM, 0);
        gemm128<<<g, 256>>>(p_x, Wk, bk, p_kn, BB * NNODE, HDDIM, DDIM, 0);
        gemm128<<<g, 256>>>(p_x, Wv, bv, p_vn, BB * NNODE, HDDIM, DDIM, 0);
        gemm128<<<g, 256>>>(p_x, Wskip, bskip, p_skip, BB * NNODE, HDDIM, DDIM, 0);
    }
    {
        dim3 g(HDDIM / 128, (BB * EEDGE) / 128);
        gemm128<<<g, 256>>>(p_ea, We, nullptr, p_ep, BB * EEDGE, HDDIM, DDIM, 0);
    }

    // 3. fused attention (softmax + aggregate + skip + relu, no atomics)
    node_attn<<<BB * NNODE, 256>>>(edge_index);

    // 4. graph representation
    {
        dim3 g(DDIM / 128, (BB * NNODE) / 128);
        gemm128<<<g, 256>>>(p_h, W1, b1, p_gr, BB * NNODE, DDIM, HDDIM, 1);
    }

    // 5. invariant path: mixed embed -> proj -> GRU
    mixed_embed<<<BB * LSEQ, 256>>>(p_invemb, emb, inv_token, inv_node, LSEQ);
    {
        dim3 g(DDIM / 128, (BB * LSEQ) / 128);
        gemm128<<<g, 256>>>(p_invemb, Wp, bp, p_invh, BB * LSEQ, DDIM, DDIM, 1);
    }
    {
        dim3 g(G3 / 64, (BB * LSEQ) / 64);
        gemm64<true><<<g, 256>>>(p_invh, W_ih, b_ih, p_gx, BB * LSEQ, G3, DDIM, 0);
    }
    gru_kernel<<<BB, G3>>>(W_hh, b_hh);

    // 6. action scoring
    mixed_embed<<<BB * AACT, 256>>>(p_aaemb, emb, aa_token, aa_node, AACT);
    aa_score<<<BB * AACT, 256>>>(Wap, bap, Wab, bab, action_mask, out);
}

// round 8
// speedup vs baseline: 1.4097x; 1.4097x over previous
#include <cuda_runtime.h>
#include <math.h>

#define BB   16
#define NNODE 1000
#define EEDGE 4000
#define DDIM 256
#define HHEAD 4
#define HDDIM 1024
#define LSEQ 64
#define AACT 128
#define OHID 256
#define G3   768

// ---------------- scratch (device globals; no allocation allowed) ----------------
__device__ float d_x[BB*NNODE*DDIM];
__device__ float d_eafeat[BB*EEDGE*DDIM];
__device__ float d_q[BB*NNODE*HDDIM];
__device__ float d_kn[BB*NNODE*HDDIM];
__device__ float d_vn[BB*NNODE*HDDIM];
__device__ float d_skip[BB*NNODE*HDDIM];
__device__ float d_ep[BB*EEDGE*HDDIM];
__device__ float d_alpha[BB*EEDGE*HHEAD];
__device__ float d_hbuf[BB*NNODE*HDDIM];
__device__ float d_gr[BB*NNODE*DDIM];
__device__ float d_invemb[BB*LSEQ*DDIM];
__device__ float d_invh[BB*LSEQ*DDIM];
__device__ float d_gx[BB*LSEQ*G3];
__device__ float d_invstate[BB*OHID];
__device__ float d_aaemb[BB*AACT*DDIM];
// CSR
__device__ int d_cnt[BB*NNODE];
__device__ int d_off[BB*NNODE];
__device__ int d_cur[BB*NNODE];
__device__ int d_elist[BB*EEDGE];

// ---------------- gathers ----------------
__global__ void gather_rows(float* __restrict__ out, const float* __restrict__ emb,
                            const int* __restrict__ idx) {
    int r = blockIdx.x;
    int t = idx[r];
    const float4* src = (const float4*)(emb + (size_t)t * DDIM);
    float4* dst = (float4*)(out + (size_t)r * DDIM);
    dst[threadIdx.x] = src[threadIdx.x];
}

__global__ void mixed_embed(float* __restrict__ out, const float* __restrict__ emb,
                            const int* __restrict__ tok, const int* __restrict__ node,
                            int perB) {
    int r = blockIdx.x;
    int b = r / perB;
    int t = tok[r];
    int nd = node[r];
    const float* e1 = emb + (size_t)t * DDIM;
    const float* e2 = d_gr + (size_t)(b * NNODE + nd) * DDIM;
    int c = threadIdx.x;
    out[(size_t)r * DDIM + c] = e1[c] + e2[c];
}

// ---------------- gemm128: C[M,N]=A[M,K]@W[K,N] (+bias)(+relu) ----------------
// 128x128x16 block tile, 256 threads, 8x8 per thread, float accumulators,
// double-buffered smem with register prefetch.
__global__ __launch_bounds__(256, 2)
void gemm128(const float* __restrict__ A, const float* __restrict__ W,
             const float* __restrict__ bias, float* __restrict__ C,
             int M, int Nn, int K, int relu) {
    __shared__ float As[2][16][132];
    __shared__ float Bs[2][16][132];
    int tid = threadIdx.x;
    int bm = blockIdx.y * 128, bn = blockIdx.x * 128;
    int tx = tid & 15, ty = tid >> 4;
    int arow = tid >> 1, ac = (tid & 1) * 8;
    int bk = tid >> 4, bc = (tid & 15) * 8;
    const float* Ag = A + (size_t)(bm + arow) * K + ac;
    const float* Wg = W + (size_t)bk * Nn + bn + bc;

    float acc[8][8];
#pragma unroll
    for (int i = 0; i < 8; i++)
#pragma unroll
        for (int j = 0; j < 8; j++) acc[i][j] = 0.f;

    // first tile -> buf 0
    float4 ra0 = *(const float4*)(Ag);
    float4 ra1 = *(const float4*)(Ag + 4);
    float4 rb0 = *(const float4*)(Wg);
    float4 rb1 = *(const float4*)(Wg + 4);
    As[0][ac + 0][arow] = ra0.x; As[0][ac + 1][arow] = ra0.y;
    As[0][ac + 2][arow] = ra0.z; As[0][ac + 3][arow] = ra0.w;
    As[0][ac + 4][arow] = ra1.x; As[0][ac + 5][arow] = ra1.y;
    As[0][ac + 6][arow] = ra1.z; As[0][ac + 7][arow] = ra1.w;
    *(float4*)&Bs[0][bk][bc] = rb0;
    *(float4*)&Bs[0][bk][bc + 4] = rb1;
    __syncthreads();

    int ntile = K >> 4;
    for (int t = 0; t < ntile; t++) {
        int buf = t & 1;
        if (t + 1 < ntile) {
            const float* Ap = Ag + (t + 1) * 16;
            const float* Wp_ = Wg + (size_t)(t + 1) * 16 * Nn;
            ra0 = *(const float4*)(Ap);
            ra1 = *(const float4*)(Ap + 4);
            rb0 = *(const float4*)(Wp_);
            rb1 = *(const float4*)(Wp_ + 4);
        }
#pragma unroll
        for (int kk = 0; kk < 16; kk++) {
            float4 A0 = *(const float4*)&As[buf][kk][ty * 4];
            float4 A1 = *(const float4*)&As[buf][kk][64 + ty * 4];
            float4 B0 = *(const float4*)&Bs[buf][kk][tx * 4];
            float4 B1 = *(const float4*)&Bs[buf][kk][64 + tx * 4];
            float av[8] = {A0.x, A0.y, A0.z, A0.w, A1.x, A1.y, A1.z, A1.w};
            float bv[8] = {B0.x, B0.y, B0.z, B0.w, B1.x, B1.y, B1.z, B1.w};
#pragma unroll
            for (int i = 0; i < 8; i++)
#pragma unroll
                for (int j = 0; j < 8; j++)
                    acc[i][j] += av[i] * bv[j];
        }
        if (t + 1 < ntile) {
            int nb = buf ^ 1;
            As[nb][ac + 0][arow] = ra0.x; As[nb][ac + 1][arow] = ra0.y;
            As[nb][ac + 2][arow] = ra0.z; As[nb][ac + 3][arow] = ra0.w;
            As[nb][ac + 4][arow] = ra1.x; As[nb][ac + 5][arow] = ra1.y;
            As[nb][ac + 6][arow] = ra1.z; As[nb][ac + 7][arow] = ra1.w;
            *(float4*)&Bs[nb][bk][bc] = rb0;
            *(float4*)&Bs[nb][bk][bc + 4] = rb1;
        }
        __syncthreads();
    }

#pragma unroll
    for (int i = 0; i < 8; i++) {
        int row = bm + ((i < 4) ? (ty * 4 + i) : (64 + ty * 4 + (i - 4)));
#pragma unroll
        for (int half = 0; half < 2; half++) {
            int col = bn + half * 64 + tx * 4;
            float o0 = acc[i][half * 4 + 0];
            float o1 = acc[i][half * 4 + 1];
            float o2 = acc[i][half * 4 + 2];
            float o3 = acc[i][half * 4 + 3];
            if (bias) {
                o0 += bias[col]; o1 += bias[col + 1];
                o2 += bias[col + 2]; o3 += bias[col + 3];
            }
            if (relu) {
                o0 = fmaxf(o0, 0.f); o1 = fmaxf(o1, 0.f);
                o2 = fmaxf(o2, 0.f); o3 = fmaxf(o3, 0.f);
            }
            *(float4*)&C[(size_t)row * Nn + col] = make_float4(o0, o1, o2, o3);
        }
    }
}

// NOTE: acc indexing maps j 0..3 -> cols tx*4..+3, j 4..7 -> cols 64+tx*4..+3
// (bv array is laid out the same way), so the epilogue above is consistent.

// ---------------- gemm64 (kept for the small W^T GEMM: gx = invh @ W_ih^T) ----------------
template<bool WT>
__global__ void gemm64(const float* __restrict__ A, const float* __restrict__ W,
                       const float* __restrict__ bias, float* __restrict__ C,
                       int M, int Nn, int K, int relu) {
    __shared__ float As[16][68];
    __shared__ float Ws[16][68];
    int tid = threadIdx.x;
    int bm = blockIdx.y * 64, bn = blockIdx.x * 64;
    int tm = (tid >> 4) * 4, tn = (tid & 15) * 4;
    float acc[4][4];
#pragma unroll
    for (int i = 0; i < 4; i++)
#pragma unroll
        for (int j = 0; j < 4; j++) acc[i][j] = 0.f;

    int la_m = tid >> 2, la_k = (tid & 3) * 4;
    for (int k0 = 0; k0 < K; k0 += 16) {
        float4 a4 = *(const float4*)&A[(size_t)(bm + la_m) * K + k0 + la_k];
        As[la_k + 0][la_m] = a4.x; As[la_k + 1][la_m] = a4.y;
        As[la_k + 2][la_m] = a4.z; As[la_k + 3][la_m] = a4.w;
        if (!WT) {
            int wk = tid >> 4, wn = (tid & 15) * 4;
            float4 w4 = *(const float4*)&W[(size_t)(k0 + wk) * Nn + bn + wn];
            *(float4*)&Ws[wk][wn] = w4;
        } else {
            int wn = tid >> 2, wk = (tid & 3) * 4;
            float4 w4 = *(const float4*)&W[(size_t)(bn + wn) * K + k0 + wk];
            Ws[wk + 0][wn] = w4.x; Ws[wk + 1][wn] = w4.y;
            Ws[wk + 2][wn] = w4.z; Ws[wk + 3][wn] = w4.w;
        }
        __syncthreads();
#pragma unroll
        for (int kk = 0; kk < 16; kk++) {
            float4 a = *(const float4*)&As[kk][tm];
            float4 w = *(const float4*)&Ws[kk][tn];
            acc[0][0] += a.x * w.x; acc[0][1] += a.x * w.y; acc[0][2] += a.x * w.z; acc[0][3] += a.x * w.w;
            acc[1][0] += a.y * w.x; acc[1][1] += a.y * w.y; acc[1][2] += a.y * w.z; acc[1][3] += a.y * w.w;
            acc[2][0] += a.z * w.x; acc[2][1] += a.z * w.y; acc[2][2] += a.z * w.z; acc[2][3] += a.z * w.w;
            acc[3][0] += a.w * w.x; acc[3][1] += a.w * w.y; acc[3][2] += a.w * w.z; acc[3][3] += a.w * w.w;
        }
        __syncthreads();
    }
#pragma unroll
    for (int i = 0; i < 4; i++) {
#pragma unroll
        for (int j = 0; j < 4; j++) {
            float v = acc[i][j];
            if (bias) v += bias[bn + tn + j];
            if (relu) v = fmaxf(v, 0.f);
            C[(size_t)(bm + tm + i) * Nn + bn + tn + j] = v;
        }
    }
}

// ---------------- CSR build ----------------
__global__ void zero_cnt() {
    int i = blockIdx.x * blockDim.x + threadIdx.x;
    if (i < BB * NNODE) d_cnt[i] = 0;
}

__global__ void count_k(const int* __restrict__ eidx) {
    int be = blockIdx.x * blockDim.x + threadIdx.x;
    if (be >= BB * EEDGE) return;
    int b = be / EEDGE, e = be - b * EEDGE;
    int dst = eidx[(size_t)(b * 2 + 1) * EEDGE + e];
    atomicAdd(&d_cnt[b * NNODE + dst], 1);
}

__global__ void scan_k() {
    __shared__ int sbuf[1024];
    __shared__ int carry;
    int t = threadIdx.x;
    if (t == 0) carry = 0;
    __syncthreads();
    for (int c = 0; c < 16; c++) {
        int i = c * 1024 + t;
        int v = (i < BB * NNODE) ? d_cnt[i] : 0;
        sbuf[t] = v;
        __syncthreads();
        for (int off = 1; off < 1024; off <<= 1) {
            int x = 0;
            if (t >= off) x = sbuf[t - off];
            __syncthreads();
            if (t >= off) sbuf[t] += x;
            __syncthreads();
        }
        if (i < BB * NNODE) {
            int excl = carry + sbuf[t] - v;
            d_off[i] = excl;
            d_cur[i] = excl;
        }
        __syncthreads();
        if (t == 1023) carry += sbuf[1023];
        __syncthreads();
    }
}

__global__ void fill_k(const int* __restrict__ eidx) {
    int be = blockIdx.x * blockDim.x + threadIdx.x;
    if (be >= BB * EEDGE) return;
    int b = be / EEDGE, e = be - b * EEDGE;
    int dst = eidx[(size_t)(b * 2 + 1) * EEDGE + e];
    int pos = atomicAdd(&d_cur[b * NNODE + dst], 1);
    d_elist[pos] = be;
}

// ---------------- fused per-node attention (alpha + softmax + aggregate + skip + relu) ----------------
__global__ void node_attn(const int* __restrict__ eidx) {
    int nid = blockIdx.x;             // b*NNODE + node
    int b = nid / NNODE;
    int t = threadIdx.x;              // 256; thread handles cols j*256+t, head j
    float* hb = d_hbuf + (size_t)nid * HDDIM;
    const float* sk = d_skip + (size_t)nid * HDDIM;
    int deg = d_cnt[nid];
    if (deg == 0) {
#pragma unroll
        for (int j = 0; j < 4; j++)
            hb[j * 256 + t] = fmaxf(sk[j * 256 + t], 0.f);
        return;
    }
    int beg = d_off[nid];
    int lane = t & 31, warp = t >> 5;

    float qv[4];
    const float* qp = d_q + (size_t)nid * HDDIM;
#pragma unroll
    for (int j = 0; j < 4; j++) qv[j] = qp[j * 256 + t];

    __shared__ float wsum[8][4];
    __shared__ float mh[4], sh[4];
    if (t < 4) { mh[t] = -3.402823466e38f; sh[t] = 0.f; }
    __syncthreads();

    // pass 1: alpha + online softmax stats
    for (int ei = beg; ei < beg + deg; ei++) {
        int be = d_elist[ei];
        int e = be - b * EEDGE;
        int src = eidx[(size_t)(b * 2) * EEDGE + e];
        const float* kp = d_kn + (size_t)(b * NNODE + src) * HDDIM;
        const float* ep = d_ep + (size_t)be * HDDIM;
        float p[4];
#pragma unroll
        for (int j = 0; j < 4; j++)
            p[j] = qv[j] * (kp[j * 256 + t] + ep[j * 256 + t]);
#pragma unroll
        for (int o = 16; o > 0; o >>= 1) {
#pragma unroll
            for (int j = 0; j < 4; j++)
                p[j] += __shfl_xor_sync(0xffffffffu, p[j], o);
        }
        if (lane == 0) {
#pragma unroll
            for (int j = 0; j < 4; j++) wsum[warp][j] = p[j];
        }
        __syncthreads();
        if (t < 4) {
            float a = 0.f;
#pragma unroll
            for (int w = 0; w < 8; w++) a += wsum[w][t];
            a *= 0.0625f;   // 1/sqrt(256)
            d_alpha[(size_t)ei * 4 + t] = a;
            float m = mh[t];
            float mn = fmaxf(m, a);
            sh[t] = sh[t] * expf(m - mn) + expf(a - mn);
            mh[t] = mn;
        }
        __syncthreads();
    }

    float m[4], sinv[4];
#pragma unroll
    for (int j = 0; j < 4; j++) { m[j] = mh[j]; sinv[j] = 1.f / sh[j]; }

    // pass 2: weighted aggregation
    float acc[4] = {0.f, 0.f, 0.f, 0.f};
    for (int ei = beg; ei < beg + deg; ei++) {
        int be = d_elist[ei];
        int e = be - b * EEDGE;
        int src = eidx[(size_t)(b * 2) * EEDGE + e];
        const float* vp = d_vn + (size_t)(b * NNODE + src) * HDDIM;
        const float* ep = d_ep + (size_t)be * HDDIM;
#pragma unroll
        for (int j = 0; j < 4; j++) {
            float w = expf(d_alpha[(size_t)ei * 4 + j] - m[j]) * sinv[j];
            acc[j] += w * (vp[j * 256 + t] + ep[j * 256 + t]);
        }
    }
#pragma unroll
    for (int j = 0; j < 4; j++)
        hb[j * 256 + t] = fmaxf(acc[j] + sk[j * 256 + t], 0.f);
}

// ---------------- GRU (one block per batch element) ----------------
__global__ void gru_kernel(const float* __restrict__ Whh, const float* __restrict__ bhh) {
    int b = blockIdx.x;
    __shared__ __align__(16) float hsh[OHID];
    __shared__ float gsh[G3];
    int t = threadIdx.x;        // 768
    if (t < OHID) hsh[t] = 0.f;
    __syncthreads();
    const float4* wr = (const float4*)(Whh + (size_t)t * OHID);
    float bg = bhh[t];
    for (int l = 0; l < LSEQ; l++) {
        float acc = bg;
#pragma unroll 8
        for (int k = 0; k < OHID / 4; k++) {
            float4 w = wr[k];
            acc += w.x * hsh[4 * k] + w.y * hsh[4 * k + 1] + w.z * hsh[4 * k + 2] + w.w * hsh[4 * k + 3];
        }
        gsh[t] = acc;
        __syncthreads();
        if (t < OHID) {
            const float* gx = d_gx + (size_t)(b * LSEQ + l) * G3;
            float r = 1.f / (1.f + expf(-(gx[t] + gsh[t])));
            float z = 1.f / (1.f + expf(-(gx[OHID + t] + gsh[OHID + t])));
            float c = tanhf(gx[2 * OHID + t] + r * gsh[2 * OHID + t]);
            hsh[t] = (1.f - z) * c + z * hsh[t];
        }
        __syncthreads();
    }
    if (t < OHID) d_invstate[b * OHID + t] = hsh[t];
}

// ---------------- final scoring ----------------
__global__ void aa_score(const float* __restrict__ Wap, const float* __restrict__ bap,
                         const float* __restrict__ Wab, const float* __restrict__ bab,
                         const float* __restrict__ mask, float* __restrict__ out) {
    int ba = blockIdx.x;                 // B*A
    int b = ba / AACT;
    __shared__ float ash[DDIM];
    __shared__ float red[DDIM];
    int o = threadIdx.x;                 // 256
    ash[o] = d_aaemb[(size_t)ba * DDIM + o];
    __syncthreads();
    float acc = 0.f;
#pragma unroll 4
    for (int dd = 0; dd < DDIM; dd++) acc += ash[dd] * Wap[(size_t)dd * OHID + o];
    float p = acc + bap[o];
    float val = p * d_invstate[b * OHID + o];
    val += ash[o] * Wab[o];
    red[o] = val;
    __syncthreads();
    for (int s = 128; s > 0; s >>= 1) {
        if (o < s) red[o] += red[o + s];
        __syncthreads();
    }
    if (o == 0) {
        float mk = fmaxf(logf(mask[ba]), -3.402823466e38f);
        out[ba] = red[0] + bab[0] + mk;
    }
}

// ---------------- launch ----------------
extern "C" void kernel_launch(void* const* d_in, const int* in_sizes, int n_in,
                              void* d_out, int out_size) {
    const int* node_tokens = (const int*)d_in[0];
    const int* edge_tokens = (const int*)d_in[1];
    const int* edge_index  = (const int*)d_in[2];
    const int* inv_token   = (const int*)d_in[3];
    const int* inv_node    = (const int*)d_in[4];
    const int* aa_token    = (const int*)d_in[5];
    const int* aa_node     = (const int*)d_in[6];
    const float* action_mask = (const float*)d_in[7];
    const float* emb  = (const float*)d_in[8];
    const float* Wq   = (const float*)d_in[9];
    const float* bq   = (const float*)d_in[10];
    const float* Wk   = (const float*)d_in[11];
    const float* bk   = (const float*)d_in[12];
    const float* Wv   = (const float*)d_in[13];
    const float* bv   = (const float*)d_in[14];
    const float* We   = (const float*)d_in[15];
    const float* Wskip = (const float*)d_in[16];
    const float* bskip = (const float*)d_in[17];
    const float* W1   = (const float*)d_in[18];
    const float* b1   = (const float*)d_in[19];
    const float* Wp   = (const float*)d_in[20];
    const float* bp   = (const float*)d_in[21];
    const float* W_ih = (const float*)d_in[22];
    const float* W_hh = (const float*)d_in[23];
    const float* b_ih = (const float*)d_in[24];
    const float* b_hh = (const float*)d_in[25];
    const float* Wab  = (const float*)d_in[26];
    const float* bab  = (const float*)d_in[27];
    const float* Wap  = (const float*)d_in[28];
    const float* bap  = (const float*)d_in[29];
    float* out = (float*)d_out;

    float* p_x      = nullptr; cudaGetSymbolAddress((void**)&p_x, d_x);
    float* p_ea     = nullptr; cudaGetSymbolAddress((void**)&p_ea, d_eafeat);
    float* p_q      = nullptr; cudaGetSymbolAddress((void**)&p_q, d_q);
    float* p_kn     = nullptr; cudaGetSymbolAddress((void**)&p_kn, d_kn);
    float* p_vn     = nullptr; cudaGetSymbolAddress((void**)&p_vn, d_vn);
    float* p_skip   = nullptr; cudaGetSymbolAddress((void**)&p_skip, d_skip);
    float* p_ep     = nullptr; cudaGetSymbolAddress((void**)&p_ep, d_ep);
    float* p_h      = nullptr; cudaGetSymbolAddress((void**)&p_h, d_hbuf);
    float* p_gr     = nullptr; cudaGetSymbolAddress((void**)&p_gr, d_gr);
    float* p_invemb = nullptr; cudaGetSymbolAddress((void**)&p_invemb, d_invemb);
    float* p_invh   = nullptr; cudaGetSymbolAddress((void**)&p_invh, d_invh);
    float* p_gx     = nullptr; cudaGetSymbolAddress((void**)&p_gx, d_gx);
    float* p_aaemb  = nullptr; cudaGetSymbolAddress((void**)&p_aaemb, d_aaemb);

    // 1. gathers
    gather_rows<<<BB * NNODE, 64>>>(p_x, emb, node_tokens);
    gather_rows<<<BB * EEDGE, 64>>>(p_ea, emb, edge_tokens);

    // CSR build (only needs edge_index)
    zero_cnt<<<(BB * NNODE + 255) / 256, 256>>>();
    count_k<<<(BB * EEDGE + 255) / 256, 256>>>(edge_index);
    scan_k<<<1, 1024>>>();
    fill_k<<<(BB * EEDGE + 255) / 256, 256>>>(edge_index);

    // 2. node / edge projections (128x128 fp32 GEMM)
    {
        dim3 g(HDDIM / 128, (BB * NNODE) / 128);
        gemm128<<<g, 256>>>(p_x, Wq, bq, p_q, BB * NNODE, HDDIM, DDIM, 0);
        gemm128<<<g, 256>>>(p_x, Wk, bk, p_kn, BB * NNODE, HDDIM, DDIM, 0);
        gemm128<<<g, 256>>>(p_x, Wv, bv, p_vn, BB * NNODE, HDDIM, DDIM, 0);
        gemm128<<<g, 256>>>(p_x, Wskip, bskip, p_skip, BB * NNODE, HDDIM, DDIM, 0);
    }
    {
        dim3 g(HDDIM / 128, (BB * EEDGE) / 128);
        gemm128<<<g, 256>>>(p_ea, We, nullptr, p_ep, BB * EEDGE, HDDIM, DDIM, 0);
    }

    // 3. fused attention (softmax + aggregate + skip + relu, no atomics)
    node_attn<<<BB * NNODE, 256>>>(edge_index);

    // 4. graph representation
    {
        dim3 g(DDIM / 128, (BB * NNODE) / 128);
        gemm128<<<g, 256>>>(p_h, W1, b1, p_gr, BB * NNODE, DDIM, HDDIM, 1);
    }

    // 5. invariant path: mixed embed -> proj -> GRU
    mixed_embed<<<BB * LSEQ, 256>>>(p_invemb, emb, inv_token, inv_node, LSEQ);
    {
        dim3 g(DDIM / 128, (BB * LSEQ) / 128);
        gemm128<<<g, 256>>>(p_invemb, Wp, bp, p_invh, BB * LSEQ, DDIM, DDIM, 1);
    }
    {
        dim3 g(G3 / 64, (BB * LSEQ) / 64);
        gemm64<true><<<g, 256>>>(p_invh, W_ih, b_ih, p_gx, BB * LSEQ, G3, DDIM, 0);
    }
    gru_kernel<<<BB, G3>>>(W_hh, b_hh);

    // 6. action scoring
    mixed_embed<<<BB * AACT, 256>>>(p_aaemb, emb, aa_token, aa_node, AACT);
    aa_score<<<BB * AACT, 256>>>(Wap, bap, Wab, bab, action_mask, out);
}